// round 1
// baseline (speedup 1.0000x reference)
#include <cuda_runtime.h>
#include <math.h>

// ---------------- problem constants ----------------
#define B      1024
#define S      10        // S0 == S1 == 10
#define P      128
#define E_DIM  32
#define H_NUM  8
#define O_DIM  32
#define D_DIM  256       // H*O
#define NMP    2
#define NCLS   8
#define KCAT   (2*D_DIM + E_DIM)   // 544

// ---------------- scratch (device globals; no allocation) ----------------
__device__ float f0_buf[B * P];                 // prep(ids)
__device__ float f1_buf[B * S * P];             // prep(n0)
__device__ float f2_buf[B * S * S * P];         // prep(n1)
__device__ float ed0_buf[B * S * E_DIM];
__device__ float ed1_buf[B * S * S * E_DIM];
__device__ float g0_buf[B * D_DIM];
__device__ float g1_buf[B * S * D_DIM];
__device__ float ed0u_buf[B * S * E_DIM];
__device__ float gout_buf[NMP * B * D_DIM];

// ---------------- prep: out[i,:] = relu(feats[idx[i]] @ Wprep) ----------------
// block = 32 rows, 256 threads. col = t&127, row-group = t>>7 handles 16 rows.
__global__ void prep_kernel(float* __restrict__ out,
                            const float* __restrict__ feats,
                            const int* __restrict__ idx,
                            const float* __restrict__ W) {
    __shared__ float4 xs[32][32];   // 32 rows x 128 floats
    const int base = blockIdx.x * 32;
    const int t = threadIdx.x;
    const float4* feats4 = (const float4*)feats;
    for (int i = t; i < 32 * 32; i += 256) {
        int r = i >> 5, c = i & 31;
        int row = idx[base + r];
        xs[r][c] = feats4[(long)row * 32 + c];
    }
    __syncthreads();
    const int col = t & 127;
    const int rg  = t >> 7;  // 0 or 1
    float acc[16];
#pragma unroll
    for (int r = 0; r < 16; r++) acc[r] = 0.f;
    for (int d4 = 0; d4 < 32; d4++) {
        const int d = d4 * 4;
        float w0 = W[(d + 0) * 128 + col];
        float w1 = W[(d + 1) * 128 + col];
        float w2 = W[(d + 2) * 128 + col];
        float w3 = W[(d + 3) * 128 + col];
#pragma unroll
        for (int r = 0; r < 16; r++) {
            float4 xv = xs[rg * 16 + r][d4];
            acc[r] += xv.x * w0 + xv.y * w1 + xv.z * w2 + xv.w * w3;
        }
    }
#pragma unroll
    for (int r = 0; r < 16; r++)
        out[(long)(base + rg * 16 + r) * 128 + col] = fmaxf(acc[r], 0.f);
}

// ---------------- edge embedding gather ----------------
__global__ void gather_edge_kernel(float* __restrict__ out,
                                   const float* __restrict__ emb,
                                   const int* __restrict__ eidx, int rows) {
    int i = blockIdx.x * blockDim.x + threadIdx.x;   // rows*8 float4 elems
    if (i < rows * 8) {
        int r = i >> 3, c = i & 7;
        ((float4*)out)[i] = ((const float4*)emb)[(long)eidx[r] * 8 + c];
    }
}

// ---------------- multi-head aggregation ----------------
// out[n, h*O+o] = relu( sum_d x[n,d]*Ws[h,d,o]
//                     + mean_s relu( sum_d neigh[n,s,d]*Wn[h,d,o]
//                                  + sum_e ed[n,s,e]*We[h,e,o] ) )
// one block per node, 256 threads, thread t -> (h = t>>5, o = t&31)
template <int DIN>
__global__ void agg_kernel(float* __restrict__ out,
                           const float* __restrict__ x,
                           const float* __restrict__ neigh,
                           const float* __restrict__ ed,
                           const float* __restrict__ Ws,
                           const float* __restrict__ Wn,
                           const float* __restrict__ We) {
    constexpr int D4 = DIN / 4;
    __shared__ float4 xs4[D4];
    __shared__ float4 ns4[S][D4];
    __shared__ float4 es4[S][E_DIM / 4];
    const int n = blockIdx.x;
    const int t = threadIdx.x;

    const float4* x4 = (const float4*)x;
    const float4* n4 = (const float4*)neigh;
    const float4* e4 = (const float4*)ed;
    for (int i = t; i < D4; i += 256) xs4[i] = x4[(long)n * D4 + i];
    for (int i = t; i < S * D4; i += 256) ((float4*)ns4)[i] = n4[(long)n * S * D4 + i];
    for (int i = t; i < S * (E_DIM / 4); i += 256) ((float4*)es4)[i] = e4[(long)n * S * (E_DIM / 4) + i];
    __syncthreads();

    const int h = t >> 5, o = t & 31;
    const float* Wn_h = Wn + (long)h * DIN * O_DIM + o;
    const float* Ws_h = Ws + (long)h * DIN * O_DIM + o;
    const float* We_h = We + (long)h * E_DIM * O_DIM + o;

    float acc[S];
#pragma unroll
    for (int s = 0; s < S; s++) acc[s] = 0.f;
    float slf = 0.f;

    for (int d4 = 0; d4 < D4; d4++) {
        const int d = d4 * 4;
        float wn0 = Wn_h[(d + 0) * O_DIM];
        float wn1 = Wn_h[(d + 1) * O_DIM];
        float wn2 = Wn_h[(d + 2) * O_DIM];
        float wn3 = Wn_h[(d + 3) * O_DIM];
        float ws0 = Ws_h[(d + 0) * O_DIM];
        float ws1 = Ws_h[(d + 1) * O_DIM];
        float ws2 = Ws_h[(d + 2) * O_DIM];
        float ws3 = Ws_h[(d + 3) * O_DIM];
        float4 xv = xs4[d4];
        slf += xv.x * ws0 + xv.y * ws1 + xv.z * ws2 + xv.w * ws3;
#pragma unroll
        for (int s = 0; s < S; s++) {
            float4 nv = ns4[s][d4];
            acc[s] += nv.x * wn0 + nv.y * wn1 + nv.z * wn2 + nv.w * wn3;
        }
    }
#pragma unroll
    for (int e4i = 0; e4i < E_DIM / 4; e4i++) {
        const int e = e4i * 4;
        float we0 = We_h[(e + 0) * O_DIM];
        float we1 = We_h[(e + 1) * O_DIM];
        float we2 = We_h[(e + 2) * O_DIM];
        float we3 = We_h[(e + 3) * O_DIM];
#pragma unroll
        for (int s = 0; s < S; s++) {
            float4 ev = es4[s][e4i];
            acc[s] += ev.x * we0 + ev.y * we1 + ev.z * we2 + ev.w * we3;
        }
    }
    float m = 0.f;
#pragma unroll
    for (int s = 0; s < S; s++) m += fmaxf(acc[s], 0.f);
    out[(long)n * D_DIM + t] = fmaxf(slf + m * (1.0f / S), 0.f);
}

// ---------------- edge update: relu(concat(src, g1, ed0) @ Wedge) ----------------
// block = 16 rows, 256 threads: col = t&31, row-group rg = t>>5 handles 2 rows
__global__ void edge_update_kernel(float* __restrict__ ed0u,
                                   const float* __restrict__ g0,
                                   const float* __restrict__ g1,
                                   const float* __restrict__ ed0,
                                   const float* __restrict__ W) {
    __shared__ __align__(16) float cs[16][KCAT];
    const int base = blockIdx.x * 16;
    const int t = threadIdx.x;
    for (int i = t; i < 16 * KCAT; i += 256) {
        int r = i / KCAT, k = i % KCAT;
        int row = base + r;
        float v;
        if (k < D_DIM)           v = g0[(long)(row / S) * D_DIM + k];
        else if (k < 2 * D_DIM)  v = g1[(long)row * D_DIM + (k - D_DIM)];
        else                     v = ed0[(long)row * E_DIM + (k - 2 * D_DIM)];
        cs[r][k] = v;
    }
    __syncthreads();
    const int col = t & 31;
    const int rg  = t >> 5;   // 8 groups x 2 rows
    float a0 = 0.f, a1 = 0.f;
    for (int k4 = 0; k4 < KCAT / 4; k4++) {
        const int k = k4 * 4;
        float w0 = W[(k + 0) * E_DIM + col];
        float w1 = W[(k + 1) * E_DIM + col];
        float w2 = W[(k + 2) * E_DIM + col];
        float w3 = W[(k + 3) * E_DIM + col];
        float4 c0 = *(const float4*)&cs[rg * 2 + 0][k];
        float4 c1 = *(const float4*)&cs[rg * 2 + 1][k];
        a0 += c0.x * w0 + c0.y * w1 + c0.z * w2 + c0.w * w3;
        a1 += c1.x * w0 + c1.y * w1 + c1.z * w2 + c1.w * w3;
    }
    ed0u[(long)(base + rg * 2 + 0) * E_DIM + col] = fmaxf(a0, 0.f);
    ed0u[(long)(base + rg * 2 + 1) * E_DIM + col] = fmaxf(a1, 0.f);
}

// ---------------- head: attention over metapaths + normalize + fc ----------------
// one block per b, 128 threads
__global__ void head_kernel(float* __restrict__ dout,
                            const float* __restrict__ gout,
                            const float* __restrict__ Wa,
                            const float* __restrict__ va,
                            const float* __restrict__ Wfc,
                            const float* __restrict__ bfc) {
    const int b = blockIdx.x, t = threadIdx.x;
    __shared__ float red[128];
    __shared__ float scores[2];
    __shared__ float sw[2];
    __shared__ float anrm[D_DIM];
    __shared__ float invn;
    const float* g0 = gout + (long)b * D_DIM;
    const float* g1 = gout + (long)B * D_DIM + (long)b * D_DIM;

    {   // scores[mp] = tanh(g @ Wa) . va
        int mp = t >> 6, j = t & 63;
        const float* g = mp ? g1 : g0;
        float hv = 0.f;
        for (int d = 0; d < D_DIM; d++) hv += g[d] * Wa[d * 64 + j];
        red[t] = tanhf(hv) * va[j];
    }
    __syncthreads();
    if (t < 2) {
        float s = 0.f;
        for (int j = 0; j < 64; j++) s += red[t * 64 + j];
        scores[t] = s;
    }
    __syncthreads();
    if (t == 0) {
        float m = fmaxf(scores[0], scores[1]);
        float e0 = expf(scores[0] - m), e1 = expf(scores[1] - m);
        float inv = 1.f / (e0 + e1);
        sw[0] = e0 * inv; sw[1] = e1 * inv;
        dout[B * NCLS + b]     = sw[0];   // weights[0, b]
        dout[B * NCLS + B + b] = sw[1];   // weights[1, b]
    }
    __syncthreads();
    float ss = 0.f;
    for (int d = t; d < D_DIM; d += 128) {
        float a = sw[0] * g0[d] + sw[1] * g1[d];
        anrm[d] = a;
        ss += a * a;
    }
    red[t] = ss;
    __syncthreads();
    for (int off = 64; off > 0; off >>= 1) {
        if (t < off) red[t] += red[t + off];
        __syncthreads();
    }
    if (t == 0) invn = 1.f / fmaxf(sqrtf(red[0]), 1e-12f);
    __syncthreads();
    {   // logits: 8 cols x 16 partial threads
        int c = t >> 4, p = t & 15;
        float acc = 0.f;
        for (int d = p; d < D_DIM; d += 16) acc += anrm[d] * invn * Wfc[d * NCLS + c];
        for (int off = 8; off > 0; off >>= 1) acc += __shfl_down_sync(0xffffffffu, acc, off, 16);
        if (p == 0) dout[b * NCLS + c] = acc + bfc[c];
    }
}

// ---------------- launch ----------------
extern "C" void kernel_launch(void* const* d_in, const int* in_sizes, int n_in,
                              void* d_out, int out_size) {
    const int*   ids      = (const int*)d_in[0];
    const int*   n0m[2]   = {(const int*)d_in[1], (const int*)d_in[5]};
    const int*   e0m[2]   = {(const int*)d_in[2], (const int*)d_in[6]};
    const int*   n1m[2]   = {(const int*)d_in[3], (const int*)d_in[7]};
    const int*   e1m[2]   = {(const int*)d_in[4], (const int*)d_in[8]};
    const float* feats    = (const float*)d_in[9];
    const float* embm[2]  = {(const float*)d_in[10], (const float*)d_in[11]};
    const float* Wprep    = (const float*)d_in[12];
    const float* Ws0      = (const float*)d_in[13];
    const float* Wn0      = (const float*)d_in[14];
    const float* We0      = (const float*)d_in[15];
    const float* Ws1      = (const float*)d_in[16];
    const float* Wn1      = (const float*)d_in[17];
    const float* We1      = (const float*)d_in[18];
    const float* Wedge0   = (const float*)d_in[19];
    const float* Wa       = (const float*)d_in[20];
    const float* va       = (const float*)d_in[21];
    const float* Wfc      = (const float*)d_in[22];
    const float* bfc      = (const float*)d_in[23];
    float*       dout     = (float*)d_out;

    float *f0, *f1, *f2, *ed0, *ed1, *g0, *g1, *ed0u, *gout;
    cudaGetSymbolAddress((void**)&f0,   f0_buf);
    cudaGetSymbolAddress((void**)&f1,   f1_buf);
    cudaGetSymbolAddress((void**)&f2,   f2_buf);
    cudaGetSymbolAddress((void**)&ed0,  ed0_buf);
    cudaGetSymbolAddress((void**)&ed1,  ed1_buf);
    cudaGetSymbolAddress((void**)&g0,   g0_buf);
    cudaGetSymbolAddress((void**)&g1,   g1_buf);
    cudaGetSymbolAddress((void**)&ed0u, ed0u_buf);
    cudaGetSymbolAddress((void**)&gout, gout_buf);

    // f0 = prep(ids): shared across metapaths (Wprep shared)
    prep_kernel<<<B / 32, 256>>>(f0, feats, ids, Wprep);

    for (int mp = 0; mp < NMP; mp++) {
        const int off_s0 = mp * H_NUM * P * O_DIM;       // 32768
        const int off_e0 = mp * H_NUM * E_DIM * O_DIM;   // 8192
        const int off_s1 = mp * H_NUM * D_DIM * O_DIM;   // 65536
        const int off_eg = mp * KCAT * E_DIM;            // 17408

        prep_kernel<<<(B * S) / 32, 256>>>(f1, feats, n0m[mp], Wprep);
        prep_kernel<<<(B * S * S) / 32, 256>>>(f2, feats, n1m[mp], Wprep);

        gather_edge_kernel<<<(B * S * 8 + 255) / 256, 256>>>(ed0, embm[mp], e0m[mp], B * S);
        gather_edge_kernel<<<(B * S * S * 8 + 255) / 256, 256>>>(ed1, embm[mp], e1m[mp], B * S * S);

        agg_kernel<128><<<B, 256>>>(g0, f0, f1, ed0,
                                    Ws0 + off_s0, Wn0 + off_s0, We0 + off_e0);
        agg_kernel<128><<<B * S, 256>>>(g1, f1, f2, ed1,
                                        Ws0 + off_s0, Wn0 + off_s0, We0 + off_e0);

        edge_update_kernel<<<(B * S) / 16, 256>>>(ed0u, g0, g1, ed0, Wedge0 + off_eg);

        agg_kernel<256><<<B, 256>>>(gout + (long)mp * B * D_DIM, g0, g1, ed0u,
                                    Ws1 + off_s1, Wn1 + off_s1, We1 + off_e0);
    }

    head_kernel<<<B, 128>>>(dout, gout, Wa, va, Wfc, bfc);
}

// round 3
// speedup vs baseline: 1.0287x; 1.0287x over previous
#include <cuda_runtime.h>
#include <math.h>

// ---------------- problem constants ----------------
#define B      1024
#define S      10        // S0 == S1 == 10
#define P      128
#define E_DIM  32
#define H_NUM  8
#define O_DIM  32
#define D_DIM  256       // H*O
#define NMP    2
#define NCLS   8
#define KCAT   (2*D_DIM + E_DIM)   // 544

typedef unsigned long long u64;

// packed f32x2 helpers (sm_100+): two independent IEEE fp32 FMAs per instruction
__device__ __forceinline__ u64 pk2(float lo, float hi) {
    u64 r; asm("mov.b64 %0,{%1,%2};" : "=l"(r) : "f"(lo), "f"(hi)); return r;
}
__device__ __forceinline__ void fma2(u64& d, u64 a, u64 b) {
    asm("fma.rn.f32x2 %0,%1,%2,%0;" : "+l"(d) : "l"(a), "l"(b));
}
__device__ __forceinline__ float sum2(u64 v) {
    float a, b; asm("mov.b64 {%0,%1},%2;" : "=f"(a), "=f"(b) : "l"(v)); return a + b;
}

// ---------------- scratch (device globals; no allocation) ----------------
__device__ float f0_buf[B * P];                 // prep(ids)
__device__ float f1_buf[B * S * P];             // prep(n0)
__device__ float f2_buf[B * S * S * P];         // prep(n1)
__device__ float ed0_buf[B * S * E_DIM];
__device__ float g0_buf[B * D_DIM];
__device__ float g1_buf[B * S * D_DIM];
__device__ float ed0u_buf[B * S * E_DIM];
__device__ float gout_buf[NMP * B * D_DIM];

// ---------------- prep: out[i,:] = relu(feats[idx[i]] @ Wprep) ----------------
// block = 32 rows, 256 threads. thread -> (colpair cp = t&63, rowgroup rg = t>>6 of 8 rows)
// packed over d: acc2[r] lanes = partial sums over even/odd d.
__global__ void prep_kernel(float* __restrict__ out,
                            const float* __restrict__ feats,
                            const int* __restrict__ idx,
                            const float* __restrict__ W) {
    __shared__ __align__(16) float xs[32 * 128];   // 32 rows x 128 floats
    const int base = blockIdx.x * 32;
    const int t = threadIdx.x;
    const float4* feats4 = (const float4*)feats;
    for (int i = t; i < 32 * 32; i += 256) {
        int r = i >> 5, c = i & 31;
        int row = idx[base + r];
        ((float4*)xs)[r * 32 + c] = feats4[(long)row * 32 + c];
    }
    __syncthreads();
    const int col = (t & 63) * 2;
    const int rg  = t >> 6;                     // 0..3, 8 rows each
    const u64* xs2 = (const u64*)xs;            // [row][64] d-pairs

    u64 acc[8][2];
#pragma unroll
    for (int r = 0; r < 8; r++) { acc[r][0] = 0ull; acc[r][1] = 0ull; }

#pragma unroll 2
    for (int d2 = 0; d2 < 64; d2++) {
        float2 wa = *(const float2*)&W[(2 * d2 + 0) * 128 + col];
        float2 wb = *(const float2*)&W[(2 * d2 + 1) * 128 + col];
        u64 w0 = pk2(wa.x, wb.x);   // (W[d][col],   W[d+1][col])
        u64 w1 = pk2(wa.y, wb.y);   // (W[d][col+1], W[d+1][col+1])
#pragma unroll
        for (int r = 0; r < 8; r++) {
            u64 xv = xs2[(rg * 8 + r) * 64 + d2];   // (x[row][d], x[row][d+1])
            fma2(acc[r][0], xv, w0);
            fma2(acc[r][1], xv, w1);
        }
    }
#pragma unroll
    for (int r = 0; r < 8; r++) {
        int row = base + rg * 8 + r;
        out[(long)row * 128 + col + 0] = fmaxf(sum2(acc[r][0]), 0.f);
        out[(long)row * 128 + col + 1] = fmaxf(sum2(acc[r][1]), 0.f);
    }
}

// ---------------- edge embedding gather (for ed0 only) ----------------
__global__ void gather_edge_kernel(float* __restrict__ out,
                                   const float* __restrict__ emb,
                                   const int* __restrict__ eidx, int rows) {
    int i = blockIdx.x * blockDim.x + threadIdx.x;   // rows*8 float4 elems
    if (i < rows * 8) {
        int r = i >> 3, c = i & 7;
        ((float4*)out)[i] = ((const float4*)emb)[(long)eidx[r] * 8 + c];
    }
}

// ---------------- multi-head aggregation (packed f32x2) ----------------
// out[n, h*O+o] = relu( x@Ws + mean_s relu( neigh@Wn + ed@We ) )
// one block per node, 128 threads: h = t>>4, output colpair op = 2*(t&15).
// packed over the reduction dim; acc2[s][col] lanes = even/odd-d partials.
// If eidx != nullptr, edge features are gathered from emb directly.
template <int DIN>
__global__ void agg_kernel(float* __restrict__ out,
                           const float* __restrict__ x,
                           const float* __restrict__ neigh,
                           const float* __restrict__ ed,
                           const int* __restrict__ eidx,
                           const float* __restrict__ emb,
                           const float* __restrict__ Ws,
                           const float* __restrict__ Wn,
                           const float* __restrict__ We) {
    constexpr int D2 = DIN / 2;
    constexpr int D4 = DIN / 4;
    __shared__ __align__(16) float xs[DIN];
    __shared__ __align__(16) float ns[S * DIN];
    __shared__ __align__(16) float es[S * E_DIM];
    const int n = blockIdx.x;
    const int t = threadIdx.x;

    for (int i = t; i < D4; i += 128)
        ((float4*)xs)[i] = ((const float4*)x)[(long)n * D4 + i];
    for (int i = t; i < S * D4; i += 128)
        ((float4*)ns)[i] = ((const float4*)neigh)[(long)n * S * D4 + i];
    if (eidx) {
        for (int i = t; i < S * (E_DIM / 4); i += 128) {
            int s = i >> 3, c = i & 7;
            ((float4*)es)[i] = ((const float4*)emb)[(long)eidx[n * S + s] * 8 + c];
        }
    } else {
        for (int i = t; i < S * (E_DIM / 4); i += 128)
            ((float4*)es)[i] = ((const float4*)ed)[(long)n * S * (E_DIM / 4) + i];
    }
    __syncthreads();

    const int h  = t >> 4;
    const int op = (t & 15) * 2;
    const float* Wn_h = Wn + (long)h * DIN * O_DIM + op;
    const float* Ws_h = Ws + (long)h * DIN * O_DIM + op;
    const float* We_h = We + (long)h * E_DIM * O_DIM + op;

    const u64* xs2 = (const u64*)xs;
    const u64* ns2 = (const u64*)ns;
    const u64* es2 = (const u64*)es;

    u64 acc[S][2];
    u64 slf[2] = {0ull, 0ull};
#pragma unroll
    for (int s = 0; s < S; s++) { acc[s][0] = 0ull; acc[s][1] = 0ull; }

#pragma unroll 2
    for (int d2 = 0; d2 < D2; d2++) {
        float2 na = *(const float2*)(Wn_h + (2 * d2 + 0) * O_DIM);
        float2 nb = *(const float2*)(Wn_h + (2 * d2 + 1) * O_DIM);
        float2 sa = *(const float2*)(Ws_h + (2 * d2 + 0) * O_DIM);
        float2 sb = *(const float2*)(Ws_h + (2 * d2 + 1) * O_DIM);
        u64 wn0 = pk2(na.x, nb.x);
        u64 wn1 = pk2(na.y, nb.y);
        u64 ws0 = pk2(sa.x, sb.x);
        u64 ws1 = pk2(sa.y, sb.y);
        u64 xv = xs2[d2];
        fma2(slf[0], xv, ws0);
        fma2(slf[1], xv, ws1);
#pragma unroll
        for (int s = 0; s < S; s++) {
            u64 nv = ns2[s * D2 + d2];
            fma2(acc[s][0], nv, wn0);
            fma2(acc[s][1], nv, wn1);
        }
    }
#pragma unroll
    for (int e2 = 0; e2 < E_DIM / 2; e2++) {
        float2 ea = *(const float2*)(We_h + (2 * e2 + 0) * O_DIM);
        float2 eb = *(const float2*)(We_h + (2 * e2 + 1) * O_DIM);
        u64 we0 = pk2(ea.x, eb.x);
        u64 we1 = pk2(ea.y, eb.y);
#pragma unroll
        for (int s = 0; s < S; s++) {
            u64 ev = es2[s * (E_DIM / 2) + e2];
            fma2(acc[s][0], ev, we0);
            fma2(acc[s][1], ev, we1);
        }
    }

    float m0 = 0.f, m1 = 0.f;
#pragma unroll
    for (int s = 0; s < S; s++) {
        m0 += fmaxf(sum2(acc[s][0]), 0.f);
        m1 += fmaxf(sum2(acc[s][1]), 0.f);
    }
    out[(long)n * D_DIM + h * O_DIM + op + 0] = fmaxf(sum2(slf[0]) + m0 * (1.0f / S), 0.f);
    out[(long)n * D_DIM + h * O_DIM + op + 1] = fmaxf(sum2(slf[1]) + m1 * (1.0f / S), 0.f);
}

// ---------------- edge update: relu(concat(src, g1, ed0) @ Wedge) ----------------
// block = 16 rows, 256 threads: colpair cp = t&15 -> cols 2cp, row r = t>>4.
__global__ void edge_update_kernel(float* __restrict__ ed0u,
                                   const float* __restrict__ g0,
                                   const float* __restrict__ g1,
                                   const float* __restrict__ ed0,
                                   const float* __restrict__ W) {
    __shared__ __align__(16) float cs[16 * KCAT];
    const int base = blockIdx.x * 16;
    const int t = threadIdx.x;
    for (int i = t; i < 16 * KCAT; i += 256) {
        int r = i / KCAT, k = i % KCAT;
        int row = base + r;
        float v;
        if (k < D_DIM)           v = g0[(long)(row / S) * D_DIM + k];
        else if (k < 2 * D_DIM)  v = g1[(long)row * D_DIM + (k - D_DIM)];
        else                     v = ed0[(long)row * E_DIM + (k - 2 * D_DIM)];
        cs[r * KCAT + k] = v;
    }
    __syncthreads();
    const int col = (t & 15) * 2;
    const int r   = t >> 4;
    const u64* cs2 = (const u64*)(cs + r * KCAT);
    u64 a0 = 0ull, a1 = 0ull;
#pragma unroll 4
    for (int k2 = 0; k2 < KCAT / 2; k2++) {
        float2 wa = *(const float2*)&W[(2 * k2 + 0) * E_DIM + col];
        float2 wb = *(const float2*)&W[(2 * k2 + 1) * E_DIM + col];
        u64 w0 = pk2(wa.x, wb.x);
        u64 w1 = pk2(wa.y, wb.y);
        u64 cv = cs2[k2];
        fma2(a0, cv, w0);
        fma2(a1, cv, w1);
    }
    ed0u[(long)(base + r) * E_DIM + col + 0] = fmaxf(sum2(a0), 0.f);
    ed0u[(long)(base + r) * E_DIM + col + 1] = fmaxf(sum2(a1), 0.f);
}

// ---------------- head: attention over metapaths + normalize + fc ----------------
__global__ void head_kernel(float* __restrict__ dout,
                            const float* __restrict__ gout,
                            const float* __restrict__ Wa,
                            const float* __restrict__ va,
                            const float* __restrict__ Wfc,
                            const float* __restrict__ bfc) {
    const int b = blockIdx.x, t = threadIdx.x;
    __shared__ float red[128];
    __shared__ float scores[2];
    __shared__ float sw[2];
    __shared__ float anrm[D_DIM];
    __shared__ float invn;
    const float* g0 = gout + (long)b * D_DIM;
    const float* g1 = gout + (long)B * D_DIM + (long)b * D_DIM;

    {   // scores[mp] = tanh(g @ Wa) . va
        int mp = t >> 6, j = t & 63;
        const float* g = mp ? g1 : g0;
        float hv = 0.f;
        for (int d = 0; d < D_DIM; d++) hv += g[d] * Wa[d * 64 + j];
        red[t] = tanhf(hv) * va[j];
    }
    __syncthreads();
    if (t < 2) {
        float s = 0.f;
        for (int j = 0; j < 64; j++) s += red[t * 64 + j];
        scores[t] = s;
    }
    __syncthreads();
    if (t == 0) {
        float m = fmaxf(scores[0], scores[1]);
        float e0 = expf(scores[0] - m), e1 = expf(scores[1] - m);
        float inv = 1.f / (e0 + e1);
        sw[0] = e0 * inv; sw[1] = e1 * inv;
        dout[B * NCLS + b]     = sw[0];   // weights[0, b]
        dout[B * NCLS + B + b] = sw[1];   // weights[1, b]
    }
    __syncthreads();
    float ss = 0.f;
    for (int d = t; d < D_DIM; d += 128) {
        float a = sw[0] * g0[d] + sw[1] * g1[d];
        anrm[d] = a;
        ss += a * a;
    }
    red[t] = ss;
    __syncthreads();
    for (int off = 64; off > 0; off >>= 1) {
        if (t < off) red[t] += red[t + off];
        __syncthreads();
    }
    if (t == 0) invn = 1.f / fmaxf(sqrtf(red[0]), 1e-12f);
    __syncthreads();
    {   // logits: 8 cols x 16 partial threads
        int c = t >> 4, p = t & 15;
        float acc = 0.f;
        for (int d = p; d < D_DIM; d += 16) acc += anrm[d] * invn * Wfc[d * NCLS + c];
        for (int off = 8; off > 0; off >>= 1) acc += __shfl_down_sync(0xffffffffu, acc, off, 16);
        if (p == 0) dout[b * NCLS + c] = acc + bfc[c];
    }
}

// ---------------- launch ----------------
extern "C" void kernel_launch(void* const* d_in, const int* in_sizes, int n_in,
                              void* d_out, int out_size) {
    const int*   ids      = (const int*)d_in[0];
    const int*   n0m[2]   = {(const int*)d_in[1], (const int*)d_in[5]};
    const int*   e0m[2]   = {(const int*)d_in[2], (const int*)d_in[6]};
    const int*   n1m[2]   = {(const int*)d_in[3], (const int*)d_in[7]};
    const int*   e1m[2]   = {(const int*)d_in[4], (const int*)d_in[8]};
    const float* feats    = (const float*)d_in[9];
    const float* embm[2]  = {(const float*)d_in[10], (const float*)d_in[11]};
    const float* Wprep    = (const float*)d_in[12];
    const float* Ws0      = (const float*)d_in[13];
    const float* Wn0      = (const float*)d_in[14];
    const float* We0      = (const float*)d_in[15];
    const float* Ws1      = (const float*)d_in[16];
    const float* Wn1      = (const float*)d_in[17];
    const float* We1      = (const float*)d_in[18];
    const float* Wedge0   = (const float*)d_in[19];
    const float* Wa       = (const float*)d_in[20];
    const float* va       = (const float*)d_in[21];
    const float* Wfc      = (const float*)d_in[22];
    const float* bfc      = (const float*)d_in[23];
    float*       dout     = (float*)d_out;

    float *f0, *f1, *f2, *ed0, *g0, *g1, *ed0u, *gout;
    cudaGetSymbolAddress((void**)&f0,   f0_buf);
    cudaGetSymbolAddress((void**)&f1,   f1_buf);
    cudaGetSymbolAddress((void**)&f2,   f2_buf);
    cudaGetSymbolAddress((void**)&ed0,  ed0_buf);
    cudaGetSymbolAddress((void**)&g0,   g0_buf);
    cudaGetSymbolAddress((void**)&g1,   g1_buf);
    cudaGetSymbolAddress((void**)&ed0u, ed0u_buf);
    cudaGetSymbolAddress((void**)&gout, gout_buf);

    // f0 = prep(ids): shared across metapaths (Wprep shared)
    prep_kernel<<<B / 32, 256>>>(f0, feats, ids, Wprep);

    for (int mp = 0; mp < NMP; mp++) {
        const int off_s0 = mp * H_NUM * P * O_DIM;       // 32768
        const int off_e0 = mp * H_NUM * E_DIM * O_DIM;   // 8192
        const int off_s1 = mp * H_NUM * D_DIM * O_DIM;   // 65536
        const int off_eg = mp * KCAT * E_DIM;            // 17408

        prep_kernel<<<(B * S) / 32, 256>>>(f1, feats, n0m[mp], Wprep);
        prep_kernel<<<(B * S * S) / 32, 256>>>(f2, feats, n1m[mp], Wprep);

        gather_edge_kernel<<<(B * S * 8 + 255) / 256, 256>>>(ed0, embm[mp], e0m[mp], B * S);

        // g0: edges from ed0 buffer; g1: edges gathered in-kernel from emb (fused)
        agg_kernel<128><<<B, 128>>>(g0, f0, f1, ed0, (const int*)nullptr, (const float*)nullptr,
                                    Ws0 + off_s0, Wn0 + off_s0, We0 + off_e0);
        agg_kernel<128><<<B * S, 128>>>(g1, f1, f2, (const float*)nullptr, e1m[mp], embm[mp],
                                        Ws0 + off_s0, Wn0 + off_s0, We0 + off_e0);

        edge_update_kernel<<<(B * S) / 16, 256>>>(ed0u, g0, g1, ed0, Wedge0 + off_eg);

        agg_kernel<256><<<B, 128>>>(gout + (long)mp * B * D_DIM, g0, g1, ed0u,
                                    (const int*)nullptr, (const float*)nullptr,
                                    Ws1 + off_s1, Wn1 + off_s1, We1 + off_e0);
    }

    head_kernel<<<B, 128>>>(dout, gout, Wa, va, Wfc, bfc);
}